// round 12
// baseline (speedup 1.0000x reference)
#include <cuda_runtime.h>
#include <cuda_fp16.h>
#include <math.h>

#define VOCAB1 50001
#define NEMB   256
#define NSEQ   64
#define NFEAT  512
#define NBATCH 1024
#define NROWS  2048

#define NTILES 392                 // ceil(50001/128)
#define VPAD   (NTILES * 128)      // 50176

// A tile, k-chunked: 8 chunks x (128 rows x 40-half pitch) = 40960 halfs/tile
#define A_CH_HALFS 5120
#define A_TILE_HALFS (8 * A_CH_HALFS)

typedef unsigned long long ull;

// ---------------- device scratch ----------------
__device__ float  g_EW[(size_t)VPAD * NFEAT];          // ~103 MB projected embeddings
__device__ __half g_U16[16 * 32768];                   // U fp16 hi/lo, 16 k-chunks, swizzled
__device__ __half g_Ah[(size_t)NTILES * A_TILE_HALFS]; // emb hi, chunked tiles
__device__ __half g_Al[(size_t)NTILES * A_TILE_HALFS]; // emb lo
__device__ __half g_W16[8 * 32768];                    // W hi/lo, 8 n-slices x 8 chunks

// ---------------- common helpers ----------------
__device__ __forceinline__ unsigned smem_u32(const void* p) {
    unsigned a;
    asm("{ .reg .u64 t; cvta.to.shared.u64 t, %1; cvt.u32.u64 %0, t; }" : "=r"(a) : "l"(p));
    return a;
}
__device__ __forceinline__ void mbar_init(unsigned a, unsigned cnt) {
    asm volatile("mbarrier.init.shared.b64 [%0], %1;" :: "r"(a), "r"(cnt) : "memory");
}
__device__ __forceinline__ void mbar_wait(unsigned a, unsigned par) {
    asm volatile(
        "{\n\t.reg .pred P;\n\t"
        "WL_%=:\n\t"
        "mbarrier.try_wait.parity.acquire.cta.shared::cta.b64 P, [%0], %1, 0x989680;\n\t"
        "@!P bra WL_%=;\n\t}"
        :: "r"(a), "r"(par) : "memory");
}
__device__ __forceinline__ void mbar_expect(unsigned a, unsigned bytes) {
    asm volatile("mbarrier.arrive.expect_tx.shared.b64 _, [%0], %1;"
                 :: "r"(a), "r"(bytes) : "memory");
}
__device__ __forceinline__ void raw_bulk(unsigned dst, const void* src,
                                         unsigned bytes, unsigned mbar) {
    asm volatile(
        "cp.async.bulk.shared::cta.global.mbarrier::complete_tx::bytes [%0], [%1], %2, [%3];"
        :: "r"(dst), "l"(src), "r"(bytes), "r"(mbar) : "memory");
}
__device__ __forceinline__ void bulk_load(unsigned dst, const void* src,
                                          unsigned bytes, unsigned mbar) {
    mbar_expect(mbar, bytes);
    raw_bulk(dst, src, bytes, mbar);
}

// ---------------- mma.sync / ldmatrix -------------------------------------
__device__ __forceinline__ void ldsm_x4(unsigned &r0, unsigned &r1,
                                        unsigned &r2, unsigned &r3, unsigned addr) {
    asm volatile("ldmatrix.sync.aligned.m8n8.x4.shared.b16 {%0,%1,%2,%3}, [%4];"
                 : "=r"(r0), "=r"(r1), "=r"(r2), "=r"(r3) : "r"(addr));
}
__device__ __forceinline__ void mma16816(float* c,
                                         unsigned a0, unsigned a1, unsigned a2, unsigned a3,
                                         unsigned b0, unsigned b1) {
    asm volatile("mma.sync.aligned.m16n8k16.row.col.f32.f16.f16.f32 "
                 "{%0,%1,%2,%3}, {%4,%5,%6,%7}, {%8,%9}, {%0,%1,%2,%3};"
                 : "+f"(c[0]), "+f"(c[1]), "+f"(c[2]), "+f"(c[3])
                 : "r"(a0), "r"(a1), "r"(a2), "r"(a3), "r"(b0), "r"(b1));
}

// U chunk swizzle (n=512 rows of 32 kk)
__device__ __forceinline__ int u_hidx(int n, int kk) {
    return n * 32 + (((((kk >> 3) + (n >> 1)) & 3)) << 3) + (kk & 7);
}
// W slice swizzle (nl in [0,64))
__device__ __forceinline__ int w_hidx(int nl, int kk) {
    return nl * 32 + (((((kk >> 3) + (nl >> 1)) & 3)) << 3) + (kk & 7);
}

// ---------------- prep: U -> fp16 hi/lo swizzled chunks -------------------
__global__ __launch_bounds__(256) void prepU_kernel(const float* __restrict__ U)
{
    int idx = blockIdx.x * 256 + threadIdx.x;
    if (idx < NFEAT * NFEAT) {
        int k = idx >> 9, n = idx & 511;
        float v = U[idx];
        __half hi = __float2half_rn(v);
        __half lo = __float2half_rn(v - __half2float(hi));
        int c = k >> 5, kk = k & 31;
        int h = u_hidx(n, kk);
        g_U16[c * 32768 + h]         = hi;
        g_U16[c * 32768 + 16384 + h] = lo;
    }
}

// ---------------- prep: emb -> fp16 hi/lo k-chunked tiles -----------------
// chunk c of tile t: [128 rows][pitch 40 halfs], only kk<32 valid.
__global__ __launch_bounds__(256) void prepA_kernel(const float* __restrict__ emb)
{
    const int t = blockIdx.x;
    const size_t base = (size_t)t * A_TILE_HALFS;
    for (int idx = threadIdx.x; idx < 128 * NEMB; idx += 256) {
        int r = idx >> 8, k = idx & 255;
        int grow = t * 128 + r;
        float v = (grow < VOCAB1) ? emb[(size_t)grow * NEMB + k] : 0.f;
        __half hi = __float2half_rn(v);
        __half lo = __float2half_rn(v - __half2float(hi));
        int c = k >> 5, kk = k & 31;
        size_t off = base + (size_t)c * A_CH_HALFS + r * 40 + kk;
        g_Ah[off] = hi;
        g_Al[off] = lo;
    }
}

// ---------------- prep: W -> fp16 hi/lo sliced/swizzled -------------------
__global__ __launch_bounds__(256) void prepW_kernel(const float* __restrict__ W)
{
    int idx = blockIdx.x * 256 + threadIdx.x;
    if (idx < NEMB * NFEAT) {
        int k = idx >> 9, n = idx & 511;          // W[k][n]
        float v = W[idx];
        __half hi = __float2half_rn(v);
        __half lo = __float2half_rn(v - __half2float(hi));
        int j = n >> 6, nl = n & 63;
        int c = k >> 5, kk = k & 31;
        int h = c * 2048 + w_hidx(nl, kk);
        g_W16[j * 32768 + h]         = hi;
        g_W16[j * 32768 + 16384 + h] = lo;
    }
}

// ---------------- Kernel 1: EW = emb @ W, pipelined mma -------------------
// grid (8 n-slices, 392 row-tiles), 256 threads. 8 k-stages x 28672B,
// double-buffered (57KB smem): load stage s+2 while computing s.
#define EWC_AH 0
#define EWC_AL 10240
#define EWC_BH 20480
#define EWC_BL 24576
#define EWC_BYTES 28672
#define EW_BUF0  1024
#define EW_TOTAL (EW_BUF0 + 2 * EWC_BYTES)   // 58368

__global__ __launch_bounds__(256) void ew_mma_kernel()
{
    extern __shared__ __align__(1024) char esm[];
    const unsigned smb = smem_u32(esm);
    const int tid  = threadIdx.x;
    const int wid  = tid >> 5;
    const int lane = tid & 31;
    const int slice = blockIdx.x;
    const int tile  = blockIdx.y;
    const unsigned mb0 = smb, mb1 = smb + 8;
    const unsigned buf0 = smb + EW_BUF0;
    const unsigned buf1 = buf0 + EWC_BYTES;

    const __half* Ah = g_Ah + (size_t)tile * A_TILE_HALFS;
    const __half* Al = g_Al + (size_t)tile * A_TILE_HALFS;
    const __half* Wp = g_W16 + (size_t)slice * 32768;

    if (tid == 0) { mbar_init(mb0, 1); mbar_init(mb1, 1); }
    __syncthreads();
    if (tid == 0) {
#pragma unroll
        for (int s = 0; s < 2; s++) {
            const unsigned mb = s ? mb1 : mb0;
            const unsigned bf = s ? buf1 : buf0;
            mbar_expect(mb, EWC_BYTES);
            raw_bulk(bf + EWC_AH, Ah + s * A_CH_HALFS, 10240, mb);
            raw_bulk(bf + EWC_AL, Al + s * A_CH_HALFS, 10240, mb);
            raw_bulk(bf + EWC_BH, Wp + s * 2048,          4096, mb);
            raw_bulk(bf + EWC_BL, Wp + 16384 + s * 2048,  4096, mb);
        }
    }

    const int a_row  = lane & 15;
    const int a_koct = (lane >> 4) * 8;
    const int b_i    = lane & 7;
    const int b_seg  = lane >> 3;
    const int b_nadd = (b_seg & 2) ? 8 : 0;
    const int b_kadd = (b_seg & 1) ? 8 : 0;

    float c[8][4];
#pragma unroll
    for (int nt = 0; nt < 8; nt++)
#pragma unroll
        for (int q = 0; q < 4; q++) c[nt][q] = 0.f;

    unsigned ph0 = 0, ph1 = 0;
#pragma unroll 1
    for (int s = 0; s < 8; s++) {
        const int bsel = s & 1;
        if (bsel) { mbar_wait(mb1, ph1); ph1 ^= 1; }
        else      { mbar_wait(mb0, ph0); ph0 ^= 1; }
        const unsigned ub = bsel ? buf1 : buf0;
#pragma unroll
        for (int kt = 0; kt < 2; kt++) {
            const int kglob = kt * 16 + a_koct;
            const unsigned aoff = (unsigned)(((wid * 16 + a_row) * 40 + kglob) * 2);
            unsigned ah[4], al[4];
            ldsm_x4(ah[0], ah[1], ah[2], ah[3], ub + EWC_AH + aoff);
            ldsm_x4(al[0], al[1], al[2], al[3], ub + EWC_AL + aoff);
            const int kk = kt * 16 + b_kadd;
#pragma unroll
            for (int p = 0; p < 4; p++) {
                const int nl = p * 16 + b_nadd + b_i;
                const unsigned boff = (unsigned)(w_hidx(nl, kk) * 2);
                unsigned bh0, bh1, bh2, bh3, bl0, bl1, bl2, bl3;
                ldsm_x4(bh0, bh1, bh2, bh3, ub + EWC_BH + boff);
                ldsm_x4(bl0, bl1, bl2, bl3, ub + EWC_BL + boff);
                mma16816(c[2 * p],     ah[0], ah[1], ah[2], ah[3], bh0, bh1);
                mma16816(c[2 * p + 1], ah[0], ah[1], ah[2], ah[3], bh2, bh3);
                mma16816(c[2 * p],     al[0], al[1], al[2], al[3], bh0, bh1);
                mma16816(c[2 * p + 1], al[0], al[1], al[2], al[3], bh2, bh3);
                mma16816(c[2 * p],     ah[0], ah[1], ah[2], ah[3], bl0, bl1);
                mma16816(c[2 * p + 1], ah[0], ah[1], ah[2], ah[3], bl2, bl3);
            }
        }
        __syncthreads();   // everyone done with this buffer
        if (tid == 0 && s + 2 < 8) {
            const int sn = s + 2;
            const unsigned mb = bsel ? mb1 : mb0;
            const unsigned bf = bsel ? buf1 : buf0;
            mbar_expect(mb, EWC_BYTES);
            raw_bulk(bf + EWC_AH, Ah + sn * A_CH_HALFS, 10240, mb);
            raw_bulk(bf + EWC_AL, Al + sn * A_CH_HALFS, 10240, mb);
            raw_bulk(bf + EWC_BH, Wp + sn * 2048,          4096, mb);
            raw_bulk(bf + EWC_BL, Wp + 16384 + sn * 2048,  4096, mb);
        }
    }

    // write-out (proven fragment mapping)
    const int grow = tile * 128 + wid * 16;
    const int r1 = lane >> 2;
    const int r2 = r1 + 8;
#pragma unroll
    for (int nt = 0; nt < 8; nt++) {
        const int col = slice * 64 + nt * 8 + (lane & 3) * 2;
        *(float2*)(g_EW + (size_t)(grow + r1) * NFEAT + col) = make_float2(c[nt][0], c[nt][1]);
        *(float2*)(g_EW + (size_t)(grow + r2) * NFEAT + col) = make_float2(c[nt][2], c[nt][3]);
    }
}

// ---------------- Kernel 2: tensor-core recurrent scan (proven R10) -------
#define RS_SID   16
#define RS_U0    1024
#define RS_U1    (RS_U0 + 65536)
#define RS_HHI   (RS_U1 + 65536)
#define RS_HLO   (RS_HHI + 16 * 536 * 2)
#define RS_TOTAL (RS_HLO + 16 * 536 * 2)

__global__ __launch_bounds__(256, 1) void rnn_tensor_kernel(
    const int*  __restrict__ ids1,
    const int*  __restrict__ ids2,
    const float* __restrict__ bias,
    float* __restrict__ out)
{
    extern __shared__ __align__(1024) char rsm[];
    const unsigned smb = smem_u32(rsm);
    const int tid  = threadIdx.x;
    const int wid  = tid >> 5;
    const int lane = tid & 31;
    const int rb0  = blockIdx.x * 16;
    const int* myids = (rb0 < NBATCH) ? ids1 : ids2;
    const int rbase  = rb0 & (NBATCH - 1);

    int* s_id = (int*)(rsm + RS_SID);
    const unsigned mb0 = smb + 0, mb1 = smb + 8;
    const unsigned ubase0 = smb + RS_U0;
    const unsigned ubase1 = smb + RS_U1;
    const unsigned hhi = smb + RS_HHI;
    const unsigned hlo = smb + RS_HLO;
    __half* h_hi = (__half*)(rsm + RS_HHI);
    __half* h_lo = (__half*)(rsm + RS_HLO);

    for (int i = tid; i < 16 * 536; i += 256) { h_hi[i] = __half(0); h_lo[i] = __half(0); }
    if (tid == 0) { mbar_init(mb0, 1); mbar_init(mb1, 1); }
    __syncthreads();
    if (tid == 0) {
        bulk_load(ubase0, g_U16,          65536, mb0);
        bulk_load(ubase1, g_U16 + 32768,  65536, mb1);
    }

    const int n0w = wid * 64;

    float2 bias2[8];
#pragma unroll
    for (int nt = 0; nt < 8; nt++)
        bias2[nt] = *(const float2*)(bias + n0w + nt * 8 + (lane & 3) * 2);

    const int a_row  = lane & 15;
    const int a_koct = (lane >> 4) * 8;
    const int b_i    = lane & 7;
    const int b_seg  = lane >> 3;
    const int b_nadd = (b_seg & 2) ? 8 : 0;
    const int b_kadd = (b_seg & 1) ? 8 : 0;

    unsigned ph0 = 0, ph1 = 0;

    for (int t = 0; t < NSEQ; t++) {
        if (tid < 16) s_id[tid] = myids[(rbase + tid) * NSEQ + t];

        float c[8][4];
#pragma unroll
        for (int nt = 0; nt < 8; nt++)
#pragma unroll
            for (int q = 0; q < 4; q++) c[nt][q] = 0.f;

#pragma unroll 1
        for (int c2 = 0; c2 < 8; c2++) {
#pragma unroll
            for (int hb = 0; hb < 2; hb++) {
                const int ck = c2 * 2 + hb;
                if (hb) { mbar_wait(mb1, ph1); ph1 ^= 1; }
                else    { mbar_wait(mb0, ph0); ph0 ^= 1; }
                const unsigned ub = hb ? ubase1 : ubase0;
#pragma unroll
                for (int kt = 0; kt < 2; kt++) {
                    const int kglob = ck * 32 + kt * 16 + a_koct;
                    unsigned ah[4], al[4];
                    const unsigned aoff = (unsigned)((a_row * 536 + kglob) * 2);
                    ldsm_x4(ah[0], ah[1], ah[2], ah[3], hhi + aoff);
                    ldsm_x4(al[0], al[1], al[2], al[3], hlo + aoff);
                    const int kk = kt * 16 + b_kadd;
#pragma unroll
                    for (int p = 0; p < 4; p++) {
                        const int n = n0w + p * 16 + b_nadd + b_i;
                        const unsigned boff = (unsigned)(u_hidx(n, kk) * 2);
                        unsigned bh0, bh1, bh2, bh3, bl0, bl1, bl2, bl3;
                        ldsm_x4(bh0, bh1, bh2, bh3, ub + boff);
                        ldsm_x4(bl0, bl1, bl2, bl3, ub + 32768 + boff);
                        mma16816(c[2 * p],     ah[0], ah[1], ah[2], ah[3], bh0, bh1);
                        mma16816(c[2 * p + 1], ah[0], ah[1], ah[2], ah[3], bh2, bh3);
                        mma16816(c[2 * p],     al[0], al[1], al[2], al[3], bh0, bh1);
                        mma16816(c[2 * p + 1], al[0], al[1], al[2], al[3], bh2, bh3);
                        mma16816(c[2 * p],     ah[0], ah[1], ah[2], ah[3], bl0, bl1);
                        mma16816(c[2 * p + 1], ah[0], ah[1], ah[2], ah[3], bl2, bl3);
                    }
                }
                __syncthreads();
                if (tid == 0) {
                    const int nc = t * 16 + ck + 2;
                    if (nc < NSEQ * 16)
                        bulk_load(hb ? ubase1 : ubase0,
                                  g_U16 + (size_t)(nc & 15) * 32768, 65536,
                                  hb ? mb1 : mb0);
                }
            }
        }

        {
            const int r1 = lane >> 2;
            const int r2 = r1 + 8;
            const int gid1 = s_id[r1], gid2 = s_id[r2];
            const float* e1 = g_EW + (size_t)gid1 * NFEAT;
            const float* e2 = g_EW + (size_t)gid2 * NFEAT;
            float2 X1[8], X2[8];
#pragma unroll
            for (int nt = 0; nt < 8; nt++) {
                const int col = n0w + nt * 8 + (lane & 3) * 2;
                X1[nt] = *(const float2*)(e1 + col);
                X2[nt] = *(const float2*)(e2 + col);
            }
            const bool m1 = (gid1 != 0), m2 = (gid2 != 0);
#pragma unroll
            for (int nt = 0; nt < 8; nt++) {
                const int col = n0w + nt * 8 + (lane & 3) * 2;
                if (m1) {
                    float v0 = tanhf(c[nt][0] + X1[nt].x + bias2[nt].x);
                    float v1 = tanhf(c[nt][1] + X1[nt].y + bias2[nt].y);
                    __half p0 = __float2half_rn(v0);
                    __half p1 = __float2half_rn(v1);
                    *(__half2*)(h_hi + r1 * 536 + col) = __halves2half2(p0, p1);
                    *(__half2*)(h_lo + r1 * 536 + col) =
                        __halves2half2(__float2half_rn(v0 - __half2float(p0)),
                                       __float2half_rn(v1 - __half2float(p1)));
                }
                if (m2) {
                    float v2 = tanhf(c[nt][2] + X2[nt].x + bias2[nt].x);
                    float v3 = tanhf(c[nt][3] + X2[nt].y + bias2[nt].y);
                    __half p2 = __float2half_rn(v2);
                    __half p3 = __float2half_rn(v3);
                    *(__half2*)(h_hi + r2 * 536 + col) = __halves2half2(p2, p3);
                    *(__half2*)(h_lo + r2 * 536 + col) =
                        __halves2half2(__float2half_rn(v2 - __half2float(p2)),
                                       __float2half_rn(v3 - __half2float(p3)));
                }
            }
        }
        __syncthreads();
    }

    for (int i = tid; i < 16 * NFEAT; i += 256) {
        const int r = i >> 9, cc = i & 511;
        out[(size_t)(rb0 + r) * NFEAT + cc] =
            __half2float(h_hi[r * 536 + cc]) + __half2float(h_lo[r * 536 + cc]);
    }
}

// ---------------- Kernel 3: cosine similarity (wider grid) ----------------
__global__ __launch_bounds__(128) void sim_kernel(float* __restrict__ out)
{
    const int b    = blockIdx.x * 4 + (threadIdx.x >> 5);
    const int lane = threadIdx.x & 31;
    const float4* s1 = (const float4*)(out + (size_t)b * NFEAT);
    const float4* s2 = (const float4*)(out + (size_t)(NBATCH + b) * NFEAT);
    float dot = 0.f, q1 = 0.f, q2 = 0.f;
#pragma unroll
    for (int j = lane; j < 128; j += 32) {
        float4 a = s1[j], c = s2[j];
        dot += a.x * c.x + a.y * c.y + a.z * c.z + a.w * c.w;
        q1  += a.x * a.x + a.y * a.y + a.z * a.z + a.w * a.w;
        q2  += c.x * c.x + c.y * c.y + c.z * c.z + c.w * c.w;
    }
#pragma unroll
    for (int o = 16; o > 0; o >>= 1) {
        dot += __shfl_xor_sync(0xffffffffu, dot, o);
        q1  += __shfl_xor_sync(0xffffffffu, q1,  o);
        q2  += __shfl_xor_sync(0xffffffffu, q2,  o);
    }
    if (lane == 0) {
        float n1 = sqrtf(fmaxf(q1, 1e-12f));
        float n2 = sqrtf(fmaxf(q2, 1e-12f));
        out[(size_t)NROWS * NFEAT + b] = dot / (n1 * n2);
    }
}

// ---------------- launch -------------------------------------------------
extern "C" void kernel_launch(void* const* d_in, const int* in_sizes, int n_in,
                              void* d_out, int out_size)
{
    (void)in_sizes; (void)n_in; (void)out_size;
    const int*   ids1 = (const int*)  d_in[0];
    const int*   ids2 = (const int*)  d_in[1];
    const float* emb  = (const float*)d_in[2];
    const float* W    = (const float*)d_in[3];
    const float* U    = (const float*)d_in[4];
    const float* bias = (const float*)d_in[5];
    float* out = (float*)d_out;

    cudaFuncSetAttribute(ew_mma_kernel,
                         cudaFuncAttributeMaxDynamicSharedMemorySize, EW_TOTAL);
    cudaFuncSetAttribute(rnn_tensor_kernel,
                         cudaFuncAttributeMaxDynamicSharedMemorySize, RS_TOTAL);

    prepU_kernel<<<(NFEAT * NFEAT + 255) / 256, 256>>>(U);
    prepA_kernel<<<NTILES, 256>>>(emb);
    prepW_kernel<<<(NEMB * NFEAT + 255) / 256, 256>>>(W);
    dim3 gew(8, NTILES);
    ew_mma_kernel<<<gew, 256, EW_TOTAL>>>();
    rnn_tensor_kernel<<<NROWS / 16, 256, RS_TOTAL>>>(ids1, ids2, bias, out);
    sim_kernel<<<NBATCH / 4, 128>>>(out);
}

// round 13
// speedup vs baseline: 1.0392x; 1.0392x over previous
#include <cuda_runtime.h>
#include <cuda_fp16.h>
#include <math.h>

#define VOCAB1 50001
#define NEMB   256
#define NSEQ   64
#define NFEAT  512
#define NBATCH 1024
#define NROWS  2048

#define NTILES 392                 // ceil(50001/128)
#define VPAD   (NTILES * 128)      // 50176

// A tile, k-chunked: 8 chunks x (128 rows x 40-half pitch)
#define A_CH_HALFS 5120
#define A_TILE_HALFS (8 * A_CH_HALFS)

typedef unsigned long long ull;

// ---------------- device scratch ----------------
__device__ float  g_EW[(size_t)VPAD * NFEAT];          // ~103 MB projected embeddings
__device__ __half g_U16[16 * 32768];                   // U fp16 hi/lo, 16 k-chunks, swizzled
__device__ __half g_Ah[(size_t)NTILES * A_TILE_HALFS]; // emb hi, chunked tiles
__device__ __half g_Al[(size_t)NTILES * A_TILE_HALFS]; // emb lo
__device__ __half g_W16[8 * 32768];                    // W hi/lo, 8 n-slices x 8 chunks

// ---------------- common helpers ----------------
__device__ __forceinline__ unsigned smem_u32(const void* p) {
    unsigned a;
    asm("{ .reg .u64 t; cvta.to.shared.u64 t, %1; cvt.u32.u64 %0, t; }" : "=r"(a) : "l"(p));
    return a;
}
__device__ __forceinline__ void mbar_init(unsigned a, unsigned cnt) {
    asm volatile("mbarrier.init.shared.b64 [%0], %1;" :: "r"(a), "r"(cnt) : "memory");
}
__device__ __forceinline__ void mbar_wait(unsigned a, unsigned par) {
    asm volatile(
        "{\n\t.reg .pred P;\n\t"
        "WL_%=:\n\t"
        "mbarrier.try_wait.parity.acquire.cta.shared::cta.b64 P, [%0], %1, 0x989680;\n\t"
        "@!P bra WL_%=;\n\t}"
        :: "r"(a), "r"(par) : "memory");
}
__device__ __forceinline__ void mbar_expect(unsigned a, unsigned bytes) {
    asm volatile("mbarrier.arrive.expect_tx.shared.b64 _, [%0], %1;"
                 :: "r"(a), "r"(bytes) : "memory");
}
__device__ __forceinline__ void raw_bulk(unsigned dst, const void* src,
                                         unsigned bytes, unsigned mbar) {
    asm volatile(
        "cp.async.bulk.shared::cta.global.mbarrier::complete_tx::bytes [%0], [%1], %2, [%3];"
        :: "r"(dst), "l"(src), "r"(bytes), "r"(mbar) : "memory");
}
__device__ __forceinline__ void bulk_load(unsigned dst, const void* src,
                                          unsigned bytes, unsigned mbar) {
    mbar_expect(mbar, bytes);
    raw_bulk(dst, src, bytes, mbar);
}

// ---------------- mma.sync / ldmatrix -------------------------------------
__device__ __forceinline__ void ldsm_x4(unsigned &r0, unsigned &r1,
                                        unsigned &r2, unsigned &r3, unsigned addr) {
    asm volatile("ldmatrix.sync.aligned.m8n8.x4.shared.b16 {%0,%1,%2,%3}, [%4];"
                 : "=r"(r0), "=r"(r1), "=r"(r2), "=r"(r3) : "r"(addr));
}
__device__ __forceinline__ void mma16816(float* c,
                                         unsigned a0, unsigned a1, unsigned a2, unsigned a3,
                                         unsigned b0, unsigned b1) {
    asm volatile("mma.sync.aligned.m16n8k16.row.col.f32.f16.f16.f32 "
                 "{%0,%1,%2,%3}, {%4,%5,%6,%7}, {%8,%9}, {%0,%1,%2,%3};"
                 : "+f"(c[0]), "+f"(c[1]), "+f"(c[2]), "+f"(c[3])
                 : "r"(a0), "r"(a1), "r"(a2), "r"(a3), "r"(b0), "r"(b1));
}

// U chunk swizzle (n=512 rows of 32 kk)
__device__ __forceinline__ int u_hidx(int n, int kk) {
    return n * 32 + (((((kk >> 3) + (n >> 1)) & 3)) << 3) + (kk & 7);
}
// W slice swizzle (nl in [0,64))
__device__ __forceinline__ int w_hidx(int nl, int kk) {
    return nl * 32 + (((((kk >> 3) + (nl >> 1)) & 3)) << 3) + (kk & 7);
}

// ---------------- prep: U -> fp16 hi/lo swizzled chunks -------------------
__global__ __launch_bounds__(256) void prepU_kernel(const float* __restrict__ U)
{
    int idx = blockIdx.x * 256 + threadIdx.x;
    if (idx < NFEAT * NFEAT) {
        int k = idx >> 9, n = idx & 511;
        float v = U[idx];
        __half hi = __float2half_rn(v);
        __half lo = __float2half_rn(v - __half2float(hi));
        int c = k >> 5, kk = k & 31;
        int h = u_hidx(n, kk);
        g_U16[c * 32768 + h]         = hi;
        g_U16[c * 32768 + 16384 + h] = lo;
    }
}

// ---------------- prep: emb -> fp16 hi/lo k-chunked tiles (half2 stores) --
__global__ __launch_bounds__(256) void prepA_kernel(const float* __restrict__ emb)
{
    const int t = blockIdx.x;
    const size_t base = (size_t)t * A_TILE_HALFS;
    for (int idx = threadIdx.x; idx < 128 * (NEMB / 2); idx += 256) {
        int r = idx >> 7, kp = idx & 127;
        int k = kp * 2;
        int grow = t * 128 + r;
        float2 v = (grow < VOCAB1)
                   ? *(const float2*)(emb + (size_t)grow * NEMB + k)
                   : make_float2(0.f, 0.f);
        __half h0 = __float2half_rn(v.x);
        __half h1 = __float2half_rn(v.y);
        __half l0 = __float2half_rn(v.x - __half2float(h0));
        __half l1 = __float2half_rn(v.y - __half2float(h1));
        int c = k >> 5, kk = k & 31;
        size_t off = base + (size_t)c * A_CH_HALFS + r * 40 + kk;
        *(__half2*)(g_Ah + off) = __halves2half2(h0, h1);
        *(__half2*)(g_Al + off) = __halves2half2(l0, l1);
    }
}

// ---------------- prep: W -> fp16 hi/lo sliced/swizzled -------------------
__global__ __launch_bounds__(256) void prepW_kernel(const float* __restrict__ W)
{
    int idx = blockIdx.x * 256 + threadIdx.x;
    if (idx < NEMB * NFEAT) {
        int k = idx >> 9, n = idx & 511;          // W[k][n]
        float v = W[idx];
        __half hi = __float2half_rn(v);
        __half lo = __float2half_rn(v - __half2float(hi));
        int j = n >> 6, nl = n & 63;
        int c = k >> 5, kk = k & 31;
        int h = c * 2048 + w_hidx(nl, kk);
        g_W16[j * 32768 + h]         = hi;
        g_W16[j * 32768 + 16384 + h] = lo;
    }
}

// ---------------- Kernel 1: EW = emb @ W, pipelined mma, 2 slices/CTA -----
// grid (4 slice-pairs, 392 row-tiles), 256 threads. 8 k-stages x 36864B,
// double-buffered (73.7KB smem): load stage s+2 while computing s.
#define EWC_AH 0
#define EWC_AL 10240
#define EWC_B  20480                  // per slice: hi 4096 + lo 4096 (x2 slices)
#define EWC_BYTES 36864
#define EW_BUF0  1024
#define EW_TOTAL (EW_BUF0 + 2 * EWC_BYTES)   // 74752

__global__ __launch_bounds__(256) void ew_mma_kernel()
{
    extern __shared__ __align__(1024) char esm[];
    const unsigned smb = smem_u32(esm);
    const int tid  = threadIdx.x;
    const int wid  = tid >> 5;
    const int lane = tid & 31;
    const int sp   = blockIdx.x;          // slice pair: slices 2sp, 2sp+1
    const int tile = blockIdx.y;
    const unsigned mb0 = smb, mb1 = smb + 8;
    const unsigned buf0 = smb + EW_BUF0;
    const unsigned buf1 = buf0 + EWC_BYTES;

    const __half* Ah = g_Ah + (size_t)tile * A_TILE_HALFS;
    const __half* Al = g_Al + (size_t)tile * A_TILE_HALFS;
    const __half* W0 = g_W16 + (size_t)(2 * sp) * 32768;
    const __half* W1 = W0 + 32768;

    if (tid == 0) { mbar_init(mb0, 1); mbar_init(mb1, 1); }
    __syncthreads();
    if (tid == 0) {
#pragma unroll
        for (int s = 0; s < 2; s++) {
            const unsigned mb = s ? mb1 : mb0;
            const unsigned bf = s ? buf1 : buf0;
            mbar_expect(mb, EWC_BYTES);
            raw_bulk(bf + EWC_AH, Ah + s * A_CH_HALFS, 10240, mb);
            raw_bulk(bf + EWC_AL, Al + s * A_CH_HALFS, 10240, mb);
            raw_bulk(bf + EWC_B,          W0 + s * 2048,         4096, mb);
            raw_bulk(bf + EWC_B + 4096,   W0 + 16384 + s * 2048, 4096, mb);
            raw_bulk(bf + EWC_B + 8192,   W1 + s * 2048,         4096, mb);
            raw_bulk(bf + EWC_B + 12288,  W1 + 16384 + s * 2048, 4096, mb);
        }
    }

    const int a_row  = lane & 15;
    const int a_koct = (lane >> 4) * 8;
    const int b_i    = lane & 7;
    const int b_seg  = lane >> 3;
    const int b_nadd = (b_seg & 2) ? 8 : 0;
    const int b_kadd = (b_seg & 1) ? 8 : 0;

    float c[2][8][4];
#pragma unroll
    for (int sl = 0; sl < 2; sl++)
#pragma unroll
        for (int nt = 0; nt < 8; nt++)
#pragma unroll
            for (int q = 0; q < 4; q++) c[sl][nt][q] = 0.f;

    unsigned ph0 = 0, ph1 = 0;
#pragma unroll 1
    for (int s = 0; s < 8; s++) {
        const int bsel = s & 1;
        if (bsel) { mbar_wait(mb1, ph1); ph1 ^= 1; }
        else      { mbar_wait(mb0, ph0); ph0 ^= 1; }
        const unsigned ub = bsel ? buf1 : buf0;
#pragma unroll
        for (int kt = 0; kt < 2; kt++) {
            const int kglob = kt * 16 + a_koct;
            const unsigned aoff = (unsigned)(((wid * 16 + a_row) * 40 + kglob) * 2);
            unsigned ah[4], al[4];
            ldsm_x4(ah[0], ah[1], ah[2], ah[3], ub + EWC_AH + aoff);
            ldsm_x4(al[0], al[1], al[2], al[3], ub + EWC_AL + aoff);
            const int kk = kt * 16 + b_kadd;
#pragma unroll
            for (int sl = 0; sl < 2; sl++) {
                const unsigned bbase = ub + EWC_B + sl * 8192;
#pragma unroll
                for (int p = 0; p < 4; p++) {
                    const int nl = p * 16 + b_nadd + b_i;
                    const unsigned boff = (unsigned)(w_hidx(nl, kk) * 2);
                    unsigned bh0, bh1, bh2, bh3, bl0, bl1, bl2, bl3;
                    ldsm_x4(bh0, bh1, bh2, bh3, bbase + boff);
                    ldsm_x4(bl0, bl1, bl2, bl3, bbase + 4096 + boff);
                    float* cp0 = c[sl][2 * p];
                    float* cp1 = c[sl][2 * p + 1];
                    mma16816(cp0, ah[0], ah[1], ah[2], ah[3], bh0, bh1);
                    mma16816(cp1, ah[0], ah[1], ah[2], ah[3], bh2, bh3);
                    mma16816(cp0, al[0], al[1], al[2], al[3], bh0, bh1);
                    mma16816(cp1, al[0], al[1], al[2], al[3], bh2, bh3);
                    mma16816(cp0, ah[0], ah[1], ah[2], ah[3], bl0, bl1);
                    mma16816(cp1, ah[0], ah[1], ah[2], ah[3], bl2, bl3);
                }
            }
        }
        __syncthreads();   // everyone done with this buffer
        if (tid == 0 && s + 2 < 8) {
            const int sn = s + 2;
            const unsigned mb = bsel ? mb1 : mb0;
            const unsigned bf = bsel ? buf1 : buf0;
            mbar_expect(mb, EWC_BYTES);
            raw_bulk(bf + EWC_AH, Ah + sn * A_CH_HALFS, 10240, mb);
            raw_bulk(bf + EWC_AL, Al + sn * A_CH_HALFS, 10240, mb);
            raw_bulk(bf + EWC_B,          W0 + sn * 2048,         4096, mb);
            raw_bulk(bf + EWC_B + 4096,   W0 + 16384 + sn * 2048, 4096, mb);
            raw_bulk(bf + EWC_B + 8192,   W1 + sn * 2048,         4096, mb);
            raw_bulk(bf + EWC_B + 12288,  W1 + 16384 + sn * 2048, 4096, mb);
        }
    }

    // write-out (proven fragment mapping), both slices
    const int grow = tile * 128 + wid * 16;
    const int r1 = lane >> 2;
    const int r2 = r1 + 8;
#pragma unroll
    for (int sl = 0; sl < 2; sl++) {
        const int colbase = (2 * sp + sl) * 64;
#pragma unroll
        for (int nt = 0; nt < 8; nt++) {
            const int col = colbase + nt * 8 + (lane & 3) * 2;
            *(float2*)(g_EW + (size_t)(grow + r1) * NFEAT + col) =
                make_float2(c[sl][nt][0], c[sl][nt][1]);
            *(float2*)(g_EW + (size_t)(grow + r2) * NFEAT + col) =
                make_float2(c[sl][nt][2], c[sl][nt][3]);
        }
    }
}

// ---------------- Kernel 2: tensor-core recurrent scan (proven R10) -------
#define RS_SID   16
#define RS_U0    1024
#define RS_U1    (RS_U0 + 65536)
#define RS_HHI   (RS_U1 + 65536)
#define RS_HLO   (RS_HHI + 16 * 536 * 2)
#define RS_TOTAL (RS_HLO + 16 * 536 * 2)

__global__ __launch_bounds__(256, 1) void rnn_tensor_kernel(
    const int*  __restrict__ ids1,
    const int*  __restrict__ ids2,
    const float* __restrict__ bias,
    float* __restrict__ out)
{
    extern __shared__ __align__(1024) char rsm[];
    const unsigned smb = smem_u32(rsm);
    const int tid  = threadIdx.x;
    const int wid  = tid >> 5;
    const int lane = tid & 31;
    const int rb0  = blockIdx.x * 16;
    const int* myids = (rb0 < NBATCH) ? ids1 : ids2;
    const int rbase  = rb0 & (NBATCH - 1);

    int* s_id = (int*)(rsm + RS_SID);
    const unsigned mb0 = smb + 0, mb1 = smb + 8;
    const unsigned ubase0 = smb + RS_U0;
    const unsigned ubase1 = smb + RS_U1;
    const unsigned hhi = smb + RS_HHI;
    const unsigned hlo = smb + RS_HLO;
    __half* h_hi = (__half*)(rsm + RS_HHI);
    __half* h_lo = (__half*)(rsm + RS_HLO);

    for (int i = tid; i < 16 * 536; i += 256) { h_hi[i] = __half(0); h_lo[i] = __half(0); }
    if (tid == 0) { mbar_init(mb0, 1); mbar_init(mb1, 1); }
    __syncthreads();
    if (tid == 0) {
        bulk_load(ubase0, g_U16,          65536, mb0);
        bulk_load(ubase1, g_U16 + 32768,  65536, mb1);
    }

    const int n0w = wid * 64;

    float2 bias2[8];
#pragma unroll
    for (int nt = 0; nt < 8; nt++)
        bias2[nt] = *(const float2*)(bias + n0w + nt * 8 + (lane & 3) * 2);

    const int a_row  = lane & 15;
    const int a_koct = (lane >> 4) * 8;
    const int b_i    = lane & 7;
    const int b_seg  = lane >> 3;
    const int b_nadd = (b_seg & 2) ? 8 : 0;
    const int b_kadd = (b_seg & 1) ? 8 : 0;

    unsigned ph0 = 0, ph1 = 0;

    for (int t = 0; t < NSEQ; t++) {
        if (tid < 16) s_id[tid] = myids[(rbase + tid) * NSEQ + t];

        float c[8][4];
#pragma unroll
        for (int nt = 0; nt < 8; nt++)
#pragma unroll
            for (int q = 0; q < 4; q++) c[nt][q] = 0.f;

#pragma unroll 1
        for (int c2 = 0; c2 < 8; c2++) {
#pragma unroll
            for (int hb = 0; hb < 2; hb++) {
                const int ck = c2 * 2 + hb;
                if (hb) { mbar_wait(mb1, ph1); ph1 ^= 1; }
                else    { mbar_wait(mb0, ph0); ph0 ^= 1; }
                const unsigned ub = hb ? ubase1 : ubase0;
#pragma unroll
                for (int kt = 0; kt < 2; kt++) {
                    const int kglob = ck * 32 + kt * 16 + a_koct;
                    unsigned ah[4], al[4];
                    const unsigned aoff = (unsigned)((a_row * 536 + kglob) * 2);
                    ldsm_x4(ah[0], ah[1], ah[2], ah[3], hhi + aoff);
                    ldsm_x4(al[0], al[1], al[2], al[3], hlo + aoff);
                    const int kk = kt * 16 + b_kadd;
#pragma unroll
                    for (int p = 0; p < 4; p++) {
                        const int n = n0w + p * 16 + b_nadd + b_i;
                        const unsigned boff = (unsigned)(u_hidx(n, kk) * 2);
                        unsigned bh0, bh1, bh2, bh3, bl0, bl1, bl2, bl3;
                        ldsm_x4(bh0, bh1, bh2, bh3, ub + boff);
                        ldsm_x4(bl0, bl1, bl2, bl3, ub + 32768 + boff);
                        mma16816(c[2 * p],     ah[0], ah[1], ah[2], ah[3], bh0, bh1);
                        mma16816(c[2 * p + 1], ah[0], ah[1], ah[2], ah[3], bh2, bh3);
                        mma16816(c[2 * p],     al[0], al[1], al[2], al[3], bh0, bh1);
                        mma16816(c[2 * p + 1], al[0], al[1], al[2], al[3], bh2, bh3);
                        mma16816(c[2 * p],     ah[0], ah[1], ah[2], ah[3], bl0, bl1);
                        mma16816(c[2 * p + 1], ah[0], ah[1], ah[2], ah[3], bl2, bl3);
                    }
                }
                __syncthreads();
                if (tid == 0) {
                    const int nc = t * 16 + ck + 2;
                    if (nc < NSEQ * 16)
                        bulk_load(hb ? ubase1 : ubase0,
                                  g_U16 + (size_t)(nc & 15) * 32768, 65536,
                                  hb ? mb1 : mb0);
                }
            }
        }

        {
            const int r1 = lane >> 2;
            const int r2 = r1 + 8;
            const int gid1 = s_id[r1], gid2 = s_id[r2];
            const float* e1 = g_EW + (size_t)gid1 * NFEAT;
            const float* e2 = g_EW + (size_t)gid2 * NFEAT;
            float2 X1[8], X2[8];
#pragma unroll
            for (int nt = 0; nt < 8; nt++) {
                const int col = n0w + nt * 8 + (lane & 3) * 2;
                X1[nt] = *(const float2*)(e1 + col);
                X2[nt] = *(const float2*)(e2 + col);
            }
            const bool m1 = (gid1 != 0), m2 = (gid2 != 0);
#pragma unroll
            for (int nt = 0; nt < 8; nt++) {
                const int col = n0w + nt * 8 + (lane & 3) * 2;
                if (m1) {
                    float v0 = tanhf(c[nt][0] + X1[nt].x + bias2[nt].x);
                    float v1 = tanhf(c[nt][1] + X1[nt].y + bias2[nt].y);
                    __half p0 = __float2half_rn(v0);
                    __half p1 = __float2half_rn(v1);
                    *(__half2*)(h_hi + r1 * 536 + col) = __halves2half2(p0, p1);
                    *(__half2*)(h_lo + r1 * 536 + col) =
                        __halves2half2(__float2half_rn(v0 - __half2float(p0)),
                                       __float2half_rn(v1 - __half2float(p1)));
                }
                if (m2) {
                    float v2 = tanhf(c[nt][2] + X2[nt].x + bias2[nt].x);
                    float v3 = tanhf(c[nt][3] + X2[nt].y + bias2[nt].y);
                    __half p2 = __float2half_rn(v2);
                    __half p3 = __float2half_rn(v3);
                    *(__half2*)(h_hi + r2 * 536 + col) = __halves2half2(p2, p3);
                    *(__half2*)(h_lo + r2 * 536 + col) =
                        __halves2half2(__float2half_rn(v2 - __half2float(p2)),
                                       __float2half_rn(v3 - __half2float(p3)));
                }
            }
        }
        __syncthreads();
    }

    for (int i = tid; i < 16 * NFEAT; i += 256) {
        const int r = i >> 9, cc = i & 511;
        out[(size_t)(rb0 + r) * NFEAT + cc] =
            __half2float(h_hi[r * 536 + cc]) + __half2float(h_lo[r * 536 + cc]);
    }
}

// ---------------- Kernel 3: cosine similarity (R11 proven) ----------------
__global__ __launch_bounds__(256) void sim_kernel(float* __restrict__ out)
{
    const int b    = blockIdx.x * 8 + (threadIdx.x >> 5);
    const int lane = threadIdx.x & 31;
    const float* s1 = out + (size_t)b * NFEAT;
    const float* s2 = out + (size_t)(NBATCH + b) * NFEAT;
    float dot = 0.f, q1 = 0.f, q2 = 0.f;
    for (int j = lane; j < NFEAT; j += 32) {
        float a = s1[j], c = s2[j];
        dot += a * c;
        q1  += a * a;
        q2  += c * c;
    }
#pragma unroll
    for (int o = 16; o > 0; o >>= 1) {
        dot += __shfl_xor_sync(0xffffffffu, dot, o);
        q1  += __shfl_xor_sync(0xffffffffu, q1,  o);
        q2  += __shfl_xor_sync(0xffffffffu, q2,  o);
    }
    if (lane == 0) {
        float n1 = sqrtf(fmaxf(q1, 1e-12f));
        float n2 = sqrtf(fmaxf(q2, 1e-12f));
        out[(size_t)NROWS * NFEAT + b] = dot / (n1 * n2);
    }
}

// ---------------- launch -------------------------------------------------
extern "C" void kernel_launch(void* const* d_in, const int* in_sizes, int n_in,
                              void* d_out, int out_size)
{
    (void)in_sizes; (void)n_in; (void)out_size;
    const int*   ids1 = (const int*)  d_in[0];
    const int*   ids2 = (const int*)  d_in[1];
    const float* emb  = (const float*)d_in[2];
    const float* W    = (const float*)d_in[3];
    const float* U    = (const float*)d_in[4];
    const float* bias = (const float*)d_in[5];
    float* out = (float*)d_out;

    cudaFuncSetAttribute(ew_mma_kernel,
                         cudaFuncAttributeMaxDynamicSharedMemorySize, EW_TOTAL);
    cudaFuncSetAttribute(rnn_tensor_kernel,
                         cudaFuncAttributeMaxDynamicSharedMemorySize, RS_TOTAL);

    prepU_kernel<<<(NFEAT * NFEAT + 255) / 256, 256>>>(U);
    prepA_kernel<<<NTILES, 256>>>(emb);
    prepW_kernel<<<(NEMB * NFEAT + 255) / 256, 256>>>(W);
    dim3 gew(4, NTILES);
    ew_mma_kernel<<<gew, 256, EW_TOTAL>>>();
    rnn_tensor_kernel<<<NROWS / 16, 256, RS_TOTAL>>>(ids1, ids2, bias, out);
    sim_kernel<<<NBATCH / 8, 256>>>(out);
}